// round 10
// baseline (speedup 1.0000x reference)
#include <cuda_runtime.h>
#include <cuda.h>
#include <cstdint>

// ============================================================================
// LoRALinear: out[T,4096] = x[T,4096] @ (W + a*A@B^T)^T + b
// sm_103 baseline ISA (no tcgen05; TMA/mbarrier = sm_90 baseline OK):
//   kernel 1: Weff = rna_tf32(W + alpha*A@B^T)  (tiled streaming, ~19us)
//   kernel 2: tf32 mma.sync GEMM; TMA -> SW128 smem, full/empty mbarrier
//             pipeline, 2 CTAs/SM; R8: rotated mainloop "MMA cur / load next"
//             with 2-deep fragment buffer so stage-boundary wait+LDSM hide
//             behind the 16 queued MMAs of k8=3.
// ============================================================================
#define KDIM 4096
#define MDIM 4096
#define RANK 8
#define LORA_ALPHA (8.0f / RANK)

#define TILE_M 128
#define TILE_N 128
#define KC 32                 // 32 floats = 128 bytes = one SW128 row
#define NSTAGES 3
#define NTHREADS 256
#define KITERS (KDIM / KC)    // 128

#define A_TILE_BYTES (TILE_M * 128)            // 16384
#define B_TILE_BYTES (TILE_N * 128)            // 16384
#define STAGE_BYTES  (A_TILE_BYTES + B_TILE_BYTES)   // 32768

#define SMEM_FULL(s)  ((s) * 16)
#define SMEM_EMPTY(s) (64 + (s) * 16)
#define SMEM_TILES    1024
#define SMEM_A(s) (SMEM_TILES + (s) * STAGE_BYTES)
#define SMEM_B(s) (SMEM_A(s) + A_TILE_BYTES)
#define SMEM_BYTES (SMEM_TILES + NSTAGES * STAGE_BYTES)   // 99328

// prep tiling
#define PREP_MT 32
#define PREP_KT 1024

__device__ float g_Weff[(size_t)MDIM * (size_t)KDIM];

// ============================================================================
// PTX helpers
// ============================================================================
#define MBARRIER_INIT(mbar, count) \
    asm volatile("mbarrier.init.shared.b64 [%0], %1;" \
                 :: "r"((uint32_t)(mbar)), "r"((uint32_t)(count)) : "memory")

#define MBARRIER_ARRIVE(mbar) \
    asm volatile("mbarrier.arrive.shared.b64 _, [%0];" \
                 :: "r"((uint32_t)(mbar)) : "memory")

#define MBARRIER_EXPECT_TX(mbar, tx_bytes) \
    asm volatile("mbarrier.arrive.expect_tx.shared.b64 _, [%0], %1;" \
                 :: "r"((uint32_t)(mbar)), "r"((uint32_t)(tx_bytes)) : "memory")

#define MBARRIER_WAIT_PARITY(mbar, phase_parity) do { \
    uint32_t _mbar = (uint32_t)(mbar); \
    uint32_t _parity = (uint32_t)(phase_parity); \
    uint32_t _done; \
    asm volatile( \
        "{\n\t" \
        ".reg .pred p;\n\t" \
        "mbarrier.try_wait.parity.acquire.cta.shared::cta.b64 p, [%1], %2;\n\t" \
        "selp.b32 %0, 1, 0, p;\n\t" \
        "}" \
        : "=r"(_done) : "r"(_mbar), "r"(_parity) : "memory"); \
    if (!_done) { \
        asm volatile( \
            "{\n\t" \
            ".reg .pred P1;\n\t" \
            "WAIT_LOOP_%=:\n\t" \
            "mbarrier.try_wait.parity.acquire.cta.shared::cta.b64 P1, [%0], %1, 0x989680;\n\t" \
            "@P1 bra.uni WAIT_DONE_%=;\n\t" \
            "bra.uni WAIT_LOOP_%=;\n\t" \
            "WAIT_DONE_%=:\n\t" \
            "}" \
            :: "r"(_mbar), "r"(_parity) : "memory"); \
    } \
} while(0)

__device__ __forceinline__ void tma_load_2d(
    uint32_t smem_addr, const void* tensor_map,
    int32_t cx, int32_t cy, uint32_t mbar
) {
    asm volatile(
        "cp.async.bulk.tensor.2d.shared::cta.global.tile.mbarrier::complete_tx::bytes "
        "[%0], [%1, {%2, %3}], [%4];"
        :: "r"(smem_addr), "l"(tensor_map), "r"(cx), "r"(cy), "r"(mbar)
        : "memory");
}

__device__ __forceinline__ void mma_tf32(float c[4], const uint32_t a[4],
                                         const uint32_t b[2]) {
    asm volatile(
        "mma.sync.aligned.m16n8k8.row.col.f32.tf32.tf32.f32 "
        "{%0,%1,%2,%3}, {%4,%5,%6,%7}, {%8,%9}, {%0,%1,%2,%3};"
        : "+f"(c[0]), "+f"(c[1]), "+f"(c[2]), "+f"(c[3])
        : "r"(a[0]), "r"(a[1]), "r"(a[2]), "r"(a[3]), "r"(b[0]), "r"(b[1]));
}

__device__ __forceinline__ void ldsm4(uint32_t r[4], uint32_t addr) {
    asm volatile("ldmatrix.sync.aligned.m8n8.x4.shared.b16 {%0,%1,%2,%3}, [%4];"
                 : "=r"(r[0]), "=r"(r[1]), "=r"(r[2]), "=r"(r[3]) : "r"(addr));
}

__device__ __forceinline__ uint32_t f2tf32(float f) {
    uint32_t o;
    asm("cvt.rna.tf32.f32 %0, %1;" : "=r"(o) : "f"(f));
    return o;
}

// ============================================================================
// Kernel 1: Weff = rna_tf32(W + alpha * A @ B^T), tiled (unchanged from R7)
// ============================================================================
__global__ void __launch_bounds__(256)
weff_prep_kernel(const float* __restrict__ W, const float* __restrict__ A,
                 const float* __restrict__ Bm, uint32_t* __restrict__ Weff) {
    __shared__ float As[PREP_MT * RANK];

    const int tid = threadIdx.x;
    const int mt = blockIdx.x / (KDIM / PREP_KT);
    const int kt = blockIdx.x % (KDIM / PREP_KT);
    const int m0 = mt * PREP_MT;
    const int k0 = kt * PREP_KT;

    if (tid < PREP_MT * RANK)
        As[tid] = A[(size_t)m0 * RANK + tid];
    __syncthreads();

    float4 b0[4], b1[4];
#pragma unroll
    for (int j = 0; j < 4; j++) {
        const float4* Brow = (const float4*)(Bm + (size_t)(k0 + tid * 4 + j) * RANK);
        b0[j] = Brow[0];
        b1[j] = Brow[1];
    }

    const size_t qbase = (size_t)(k0 >> 2) + tid;
#pragma unroll 4
    for (int q = 0; q < PREP_MT; q++) {
        const int m = m0 + q;
        const float4* Ar = (const float4*)(As + q * RANK);
        float4 a0 = Ar[0], a1 = Ar[1];
        size_t off = (size_t)m * (KDIM / 4) + qbase;
        float4 w = ((const float4*)W)[off];
        float r[4];
#pragma unroll
        for (int j = 0; j < 4; j++) {
            r[j] = a0.x * b0[j].x + a0.y * b0[j].y + a0.z * b0[j].z + a0.w * b0[j].w
                 + a1.x * b1[j].x + a1.y * b1[j].y + a1.z * b1[j].z + a1.w * b1[j].w;
        }
        uint4 o;
        o.x = f2tf32(w.x + LORA_ALPHA * r[0]);
        o.y = f2tf32(w.y + LORA_ALPHA * r[1]);
        o.z = f2tf32(w.z + LORA_ALPHA * r[2]);
        o.w = f2tf32(w.w + LORA_ALPHA * r[3]);
        ((uint4*)Weff)[off] = o;
    }
}

// ============================================================================
// Kernel 2: C = x @ Weff^T + b   (R8: rotated pipelined mainloop)
// ============================================================================
struct Frags {
    uint32_t a[4][4];
    uint32_t b[4][2];
};

__global__ void __launch_bounds__(NTHREADS, 2)
lora_gemm_kernel(const __grid_constant__ CUtensorMap tmx,
                 const __grid_constant__ CUtensorMap tmw,
                 const float* __restrict__ bias, float* __restrict__ out) {
    extern __shared__ __align__(1024) char smem[];
    uint32_t sb;
    asm("{ .reg .u64 t; cvta.to.shared.u64 t, %1; cvt.u32.u64 %0, t; }"
        : "=r"(sb) : "l"(smem));

    const int tid = threadIdx.x;
    const int wid = tid >> 5;
    const int lid = tid & 31;
    const int gid = lid >> 2;
    const int qid = lid & 3;

    const int n0 = blockIdx.x * TILE_N;
    const int m0 = blockIdx.y * TILE_M;

    const int wm0 = (wid & 1) * 64;       // 2 warps over M
    const int wn0 = (wid >> 1) * 32;      // 4 warps over N

    const int a_row  = wm0 + (lid & 15);
    const int a_k4   = (lid >> 4) * 16;
    const uint32_t a_swz = (uint32_t)((a_row & 7) << 4);
    const int b_row  = wn0 + (lid & 7) + ((lid >> 4) * 8);
    const int b_k4   = ((lid >> 3) & 1) * 16;
    const uint32_t b_swz = (uint32_t)((b_row & 7) << 4);

    if (tid == 0) {
        for (int s = 0; s < NSTAGES; s++) {
            MBARRIER_INIT(sb + SMEM_FULL(s), 1);
            MBARRIER_INIT(sb + SMEM_EMPTY(s), 8);
        }
    }
    __syncthreads();

    if (tid == 0) {
#pragma unroll
        for (int p = 0; p < 2; p++) {
            MBARRIER_EXPECT_TX(sb + SMEM_FULL(p), STAGE_BYTES);
            tma_load_2d(sb + SMEM_A(p), &tmx, p * KC, m0, sb + SMEM_FULL(p));
            tma_load_2d(sb + SMEM_B(p), &tmw, p * KC, n0, sb + SMEM_FULL(p));
        }
    }

    float acc[4][4][4];
#pragma unroll
    for (int i = 0; i < 4; i++)
#pragma unroll
        for (int j = 0; j < 4; j++)
#pragma unroll
            for (int e = 0; e < 4; e++) acc[i][j][e] = 0.0f;

    // fragment load: (k8 chunk kb4 = k8*32 bytes)
    auto load_frags = [&](Frags& f, uint32_t sA, uint32_t sB, int k8) {
        const uint32_t kb4 = (uint32_t)(k8 * 32);
        const uint32_t ca = (kb4 + a_k4) ^ a_swz;
        const uint32_t cb = (kb4 + b_k4) ^ b_swz;
#pragma unroll
        for (int i = 0; i < 4; i++)
            ldsm4(f.a[i], sA + (a_row + i * 16) * 128 + ca);
#pragma unroll
        for (int p = 0; p < 2; p++) {
            uint32_t t[4];
            ldsm4(t, sB + (b_row + p * 16) * 128 + cb);
            f.b[2 * p][0]     = t[0];
            f.b[2 * p][1]     = t[1];
            f.b[2 * p + 1][0] = t[2];
            f.b[2 * p + 1][1] = t[3];
        }
    };

    auto mma16 = [&](const Frags& f) {
#pragma unroll
        for (int i = 0; i < 4; i++)
#pragma unroll
            for (int j = 0; j < 4; j++)
                mma_tf32(acc[i][j], f.a[i], f.b[j]);
    };

    int cs = 0, cph = 0;
    int ps = 2, pph = 1;

    // ---- pipeline prologue: wait stage 0, load its first fragment block ----
    MBARRIER_WAIT_PARITY(sb + SMEM_FULL(0), 0);
    uint32_t sA = sb + SMEM_A(0);
    uint32_t sB = sb + SMEM_B(0);

    Frags f0, f1;
    load_frags(f0, sA, sB, 0);

#pragma unroll 1
    for (int kc = 0; kc < KITERS; kc++) {
        // producer: thread 0 issues stage kc+2
        if (tid == 0 && kc + 2 < KITERS) {
            MBARRIER_WAIT_PARITY(sb + SMEM_EMPTY(ps), pph);
            MBARRIER_EXPECT_TX(sb + SMEM_FULL(ps), STAGE_BYTES);
            tma_load_2d(sb + SMEM_A(ps), &tmx, (kc + 2) * KC, m0, sb + SMEM_FULL(ps));
            tma_load_2d(sb + SMEM_B(ps), &tmw, (kc + 2) * KC, n0, sb + SMEM_FULL(ps));
            if (++ps == NSTAGES) { ps = 0; pph ^= 1; }
        }

        // rotated body: MMA current block, load next block behind it
        mma16(f0); load_frags(f1, sA, sB, 1);   // k8 = 0
        mma16(f1); load_frags(f0, sA, sB, 2);   // k8 = 1
        mma16(f0); load_frags(f1, sA, sB, 3);   // k8 = 2
        mma16(f1);                               // k8 = 3 (16 MMAs queued)

        // stage cs fully consumed (scoreboard drained by mma16 above)
        if (lid == 0) MBARRIER_ARRIVE(sb + SMEM_EMPTY(cs));
        if (++cs == NSTAGES) { cs = 0; cph ^= 1; }

        // cross-boundary prefetch hides wait+LDSM behind queued MMAs
        if (kc + 1 < KITERS) {
            MBARRIER_WAIT_PARITY(sb + SMEM_FULL(cs), cph);
            sA = sb + SMEM_A(cs);
            sB = sb + SMEM_B(cs);
            load_frags(f0, sA, sB, 0);
        }
    }

    // --- epilogue: acc + bias -> out ---
#pragma unroll
    for (int j = 0; j < 4; j++) {
        int col = n0 + wn0 + j * 8 + qid * 2;
        float2 bb = *(const float2*)(bias + col);
#pragma unroll
        for (int i = 0; i < 4; i++) {
            int row = m0 + wm0 + i * 16 + gid;
            float2 v0 = make_float2(acc[i][j][0] + bb.x, acc[i][j][1] + bb.y);
            float2 v1 = make_float2(acc[i][j][2] + bb.x, acc[i][j][3] + bb.y);
            *(float2*)(out + (size_t)row * MDIM + col) = v0;
            *(float2*)(out + (size_t)(row + 8) * MDIM + col) = v1;
        }
    }
}

// ============================================================================
// Host launch
// ============================================================================
typedef CUresult (*EncodeTiledFn)(
    CUtensorMap*, CUtensorMapDataType, cuuint32_t, void*,
    const cuuint64_t*, const cuuint64_t*, const cuuint32_t*, const cuuint32_t*,
    CUtensorMapInterleave, CUtensorMapSwizzle, CUtensorMapL2promotion,
    CUtensorMapFloatOOBfill);

static void make_map_2d(CUtensorMap* tm, const void* ptr,
                        unsigned long long d0, unsigned long long d1) {
    EncodeTiledFn fn = nullptr;
    cudaDriverEntryPointQueryResult qr;
    cudaGetDriverEntryPoint("cuTensorMapEncodeTiled", (void**)&fn,
                            cudaEnableDefault, &qr);
    cuuint64_t dims[2]    = {d0, d1};
    cuuint64_t strides[1] = {d0 * sizeof(float)};
    cuuint32_t box[2]     = {KC, TILE_M};
    cuuint32_t es[2]      = {1, 1};
    fn(tm, CU_TENSOR_MAP_DATA_TYPE_FLOAT32, 2, (void*)ptr, dims, strides, box, es,
       CU_TENSOR_MAP_INTERLEAVE_NONE, CU_TENSOR_MAP_SWIZZLE_128B,
       CU_TENSOR_MAP_L2_PROMOTION_L2_128B, CU_TENSOR_MAP_FLOAT_OOB_FILL_NONE);
}

extern "C" void kernel_launch(void* const* d_in, const int* in_sizes, int n_in,
                              void* d_out, int out_size) {
    const float* x = (const float*)d_in[0];
    const float* W = (const float*)d_in[1];
    const float* b = (const float*)d_in[2];
    const float* A = (const float*)d_in[3];
    const float* B = (const float*)d_in[4];
    float* out = (float*)d_out;
    int T = in_sizes[0] / KDIM;

    void* weff_ptr = nullptr;
    cudaGetSymbolAddress(&weff_ptr, g_Weff);

    int prep_blocks = (MDIM / PREP_MT) * (KDIM / PREP_KT);
    weff_prep_kernel<<<prep_blocks, 256>>>(W, A, B, (uint32_t*)weff_ptr);

    CUtensorMap tmx, tmw;
    make_map_2d(&tmx, x, KDIM, (unsigned long long)T);
    make_map_2d(&tmw, weff_ptr, KDIM, MDIM);

    cudaFuncSetAttribute(lora_gemm_kernel,
                         cudaFuncAttributeMaxDynamicSharedMemorySize, SMEM_BYTES);

    dim3 grid(MDIM / TILE_N, T / TILE_M);
    lora_gemm_kernel<<<grid, NTHREADS, SMEM_BYTES>>>(tmx, tmw, b, out);
}

// round 11
// speedup vs baseline: 1.0018x; 1.0018x over previous
#include <cuda_runtime.h>
#include <cuda.h>
#include <cstdint>

// ============================================================================
// LoRALinear: out[T,4096] = x[T,4096] @ (W + a*A@B^T)^T + b
// sm_103 baseline ISA (no tcgen05; TMA/mbarrier = sm_90 baseline OK):
//   kernel 1: Weff = rna_tf32(W + alpha*A@B^T)  (tiled streaming, ~19us)
//   kernel 2: tf32 mma.sync GEMM; TMA -> SW128 smem, full/empty mbarrier
//             pipeline, 2 CTAs/SM; R8: rotated mainloop "MMA cur / load next"
//             with 2-deep fragment buffer so stage-boundary wait+LDSM hide
//             behind the 16 queued MMAs of k8=3.
// ============================================================================
#define KDIM 4096
#define MDIM 4096
#define RANK 8
#define LORA_ALPHA (8.0f / RANK)

#define TILE_M 128
#define TILE_N 128
#define KC 32                 // 32 floats = 128 bytes = one SW128 row
#define NSTAGES 3
#define NTHREADS 256
#define KITERS (KDIM / KC)    // 128

#define A_TILE_BYTES (TILE_M * 128)            // 16384
#define B_TILE_BYTES (TILE_N * 128)            // 16384
#define STAGE_BYTES  (A_TILE_BYTES + B_TILE_BYTES)   // 32768

#define SMEM_FULL(s)  ((s) * 16)
#define SMEM_EMPTY(s) (64 + (s) * 16)
#define SMEM_TILES    1024
#define SMEM_A(s) (SMEM_TILES + (s) * STAGE_BYTES)
#define SMEM_B(s) (SMEM_A(s) + A_TILE_BYTES)
#define SMEM_BYTES (SMEM_TILES + NSTAGES * STAGE_BYTES)   // 99328

// prep tiling
#define PREP_MT 32
#define PREP_KT 1024

__device__ float g_Weff[(size_t)MDIM * (size_t)KDIM];

// ============================================================================
// PTX helpers
// ============================================================================
#define MBARRIER_INIT(mbar, count) \
    asm volatile("mbarrier.init.shared.b64 [%0], %1;" \
                 :: "r"((uint32_t)(mbar)), "r"((uint32_t)(count)) : "memory")

#define MBARRIER_ARRIVE(mbar) \
    asm volatile("mbarrier.arrive.shared.b64 _, [%0];" \
                 :: "r"((uint32_t)(mbar)) : "memory")

#define MBARRIER_EXPECT_TX(mbar, tx_bytes) \
    asm volatile("mbarrier.arrive.expect_tx.shared.b64 _, [%0], %1;" \
                 :: "r"((uint32_t)(mbar)), "r"((uint32_t)(tx_bytes)) : "memory")

#define MBARRIER_WAIT_PARITY(mbar, phase_parity) do { \
    uint32_t _mbar = (uint32_t)(mbar); \
    uint32_t _parity = (uint32_t)(phase_parity); \
    uint32_t _done; \
    asm volatile( \
        "{\n\t" \
        ".reg .pred p;\n\t" \
        "mbarrier.try_wait.parity.acquire.cta.shared::cta.b64 p, [%1], %2;\n\t" \
        "selp.b32 %0, 1, 0, p;\n\t" \
        "}" \
        : "=r"(_done) : "r"(_mbar), "r"(_parity) : "memory"); \
    if (!_done) { \
        asm volatile( \
            "{\n\t" \
            ".reg .pred P1;\n\t" \
            "WAIT_LOOP_%=:\n\t" \
            "mbarrier.try_wait.parity.acquire.cta.shared::cta.b64 P1, [%0], %1, 0x989680;\n\t" \
            "@P1 bra.uni WAIT_DONE_%=;\n\t" \
            "bra.uni WAIT_LOOP_%=;\n\t" \
            "WAIT_DONE_%=:\n\t" \
            "}" \
            :: "r"(_mbar), "r"(_parity) : "memory"); \
    } \
} while(0)

__device__ __forceinline__ void tma_load_2d(
    uint32_t smem_addr, const void* tensor_map,
    int32_t cx, int32_t cy, uint32_t mbar
) {
    asm volatile(
        "cp.async.bulk.tensor.2d.shared::cta.global.tile.mbarrier::complete_tx::bytes "
        "[%0], [%1, {%2, %3}], [%4];"
        :: "r"(smem_addr), "l"(tensor_map), "r"(cx), "r"(cy), "r"(mbar)
        : "memory");
}

__device__ __forceinline__ void mma_tf32(float c[4], const uint32_t a[4],
                                         const uint32_t b[2]) {
    asm volatile(
        "mma.sync.aligned.m16n8k8.row.col.f32.tf32.tf32.f32 "
        "{%0,%1,%2,%3}, {%4,%5,%6,%7}, {%8,%9}, {%0,%1,%2,%3};"
        : "+f"(c[0]), "+f"(c[1]), "+f"(c[2]), "+f"(c[3])
        : "r"(a[0]), "r"(a[1]), "r"(a[2]), "r"(a[3]), "r"(b[0]), "r"(b[1]));
}

__device__ __forceinline__ void ldsm4(uint32_t r[4], uint32_t addr) {
    asm volatile("ldmatrix.sync.aligned.m8n8.x4.shared.b16 {%0,%1,%2,%3}, [%4];"
                 : "=r"(r[0]), "=r"(r[1]), "=r"(r[2]), "=r"(r[3]) : "r"(addr));
}

__device__ __forceinline__ uint32_t f2tf32(float f) {
    uint32_t o;
    asm("cvt.rna.tf32.f32 %0, %1;" : "=r"(o) : "f"(f));
    return o;
}

// ============================================================================
// Kernel 1: Weff = rna_tf32(W + alpha * A @ B^T), tiled (unchanged from R7)
// ============================================================================
__global__ void __launch_bounds__(256)
weff_prep_kernel(const float* __restrict__ W, const float* __restrict__ A,
                 const float* __restrict__ Bm, uint32_t* __restrict__ Weff) {
    __shared__ float As[PREP_MT * RANK];

    const int tid = threadIdx.x;
    const int mt = blockIdx.x / (KDIM / PREP_KT);
    const int kt = blockIdx.x % (KDIM / PREP_KT);
    const int m0 = mt * PREP_MT;
    const int k0 = kt * PREP_KT;

    if (tid < PREP_MT * RANK)
        As[tid] = A[(size_t)m0 * RANK + tid];
    __syncthreads();

    float4 b0[4], b1[4];
#pragma unroll
    for (int j = 0; j < 4; j++) {
        const float4* Brow = (const float4*)(Bm + (size_t)(k0 + tid * 4 + j) * RANK);
        b0[j] = Brow[0];
        b1[j] = Brow[1];
    }

    const size_t qbase = (size_t)(k0 >> 2) + tid;
#pragma unroll 4
    for (int q = 0; q < PREP_MT; q++) {
        const int m = m0 + q;
        const float4* Ar = (const float4*)(As + q * RANK);
        float4 a0 = Ar[0], a1 = Ar[1];
        size_t off = (size_t)m * (KDIM / 4) + qbase;
        float4 w = ((const float4*)W)[off];
        float r[4];
#pragma unroll
        for (int j = 0; j < 4; j++) {
            r[j] = a0.x * b0[j].x + a0.y * b0[j].y + a0.z * b0[j].z + a0.w * b0[j].w
                 + a1.x * b1[j].x + a1.y * b1[j].y + a1.z * b1[j].z + a1.w * b1[j].w;
        }
        uint4 o;
        o.x = f2tf32(w.x + LORA_ALPHA * r[0]);
        o.y = f2tf32(w.y + LORA_ALPHA * r[1]);
        o.z = f2tf32(w.z + LORA_ALPHA * r[2]);
        o.w = f2tf32(w.w + LORA_ALPHA * r[3]);
        ((uint4*)Weff)[off] = o;
    }
}

// ============================================================================
// Kernel 2: C = x @ Weff^T + b   (R8: rotated pipelined mainloop)
// ============================================================================
struct Frags {
    uint32_t a[4][4];
    uint32_t b[4][2];
};

__global__ void __launch_bounds__(NTHREADS, 2)
lora_gemm_kernel(const __grid_constant__ CUtensorMap tmx,
                 const __grid_constant__ CUtensorMap tmw,
                 const float* __restrict__ bias, float* __restrict__ out) {
    extern __shared__ __align__(1024) char smem[];
    uint32_t sb;
    asm("{ .reg .u64 t; cvta.to.shared.u64 t, %1; cvt.u32.u64 %0, t; }"
        : "=r"(sb) : "l"(smem));

    const int tid = threadIdx.x;
    const int wid = tid >> 5;
    const int lid = tid & 31;
    const int gid = lid >> 2;
    const int qid = lid & 3;

    const int n0 = blockIdx.x * TILE_N;
    const int m0 = blockIdx.y * TILE_M;

    const int wm0 = (wid & 1) * 64;       // 2 warps over M
    const int wn0 = (wid >> 1) * 32;      // 4 warps over N

    const int a_row  = wm0 + (lid & 15);
    const int a_k4   = (lid >> 4) * 16;
    const uint32_t a_swz = (uint32_t)((a_row & 7) << 4);
    const int b_row  = wn0 + (lid & 7) + ((lid >> 4) * 8);
    const int b_k4   = ((lid >> 3) & 1) * 16;
    const uint32_t b_swz = (uint32_t)((b_row & 7) << 4);

    if (tid == 0) {
        for (int s = 0; s < NSTAGES; s++) {
            MBARRIER_INIT(sb + SMEM_FULL(s), 1);
            MBARRIER_INIT(sb + SMEM_EMPTY(s), 8);
        }
    }
    __syncthreads();

    if (tid == 0) {
#pragma unroll
        for (int p = 0; p < 2; p++) {
            MBARRIER_EXPECT_TX(sb + SMEM_FULL(p), STAGE_BYTES);
            tma_load_2d(sb + SMEM_A(p), &tmx, p * KC, m0, sb + SMEM_FULL(p));
            tma_load_2d(sb + SMEM_B(p), &tmw, p * KC, n0, sb + SMEM_FULL(p));
        }
    }

    float acc[4][4][4];
#pragma unroll
    for (int i = 0; i < 4; i++)
#pragma unroll
        for (int j = 0; j < 4; j++)
#pragma unroll
            for (int e = 0; e < 4; e++) acc[i][j][e] = 0.0f;

    // fragment load: (k8 chunk kb4 = k8*32 bytes)
    auto load_frags = [&](Frags& f, uint32_t sA, uint32_t sB, int k8) {
        const uint32_t kb4 = (uint32_t)(k8 * 32);
        const uint32_t ca = (kb4 + a_k4) ^ a_swz;
        const uint32_t cb = (kb4 + b_k4) ^ b_swz;
#pragma unroll
        for (int i = 0; i < 4; i++)
            ldsm4(f.a[i], sA + (a_row + i * 16) * 128 + ca);
#pragma unroll
        for (int p = 0; p < 2; p++) {
            uint32_t t[4];
            ldsm4(t, sB + (b_row + p * 16) * 128 + cb);
            f.b[2 * p][0]     = t[0];
            f.b[2 * p][1]     = t[1];
            f.b[2 * p + 1][0] = t[2];
            f.b[2 * p + 1][1] = t[3];
        }
    };

    auto mma16 = [&](const Frags& f) {
#pragma unroll
        for (int i = 0; i < 4; i++)
#pragma unroll
            for (int j = 0; j < 4; j++)
                mma_tf32(acc[i][j], f.a[i], f.b[j]);
    };

    int cs = 0, cph = 0;
    int ps = 2, pph = 1;

    // ---- pipeline prologue: wait stage 0, load its first fragment block ----
    MBARRIER_WAIT_PARITY(sb + SMEM_FULL(0), 0);
    uint32_t sA = sb + SMEM_A(0);
    uint32_t sB = sb + SMEM_B(0);

    Frags f0, f1;
    load_frags(f0, sA, sB, 0);

#pragma unroll 1
    for (int kc = 0; kc < KITERS; kc++) {
        // producer: thread 0 issues stage kc+2
        if (tid == 0 && kc + 2 < KITERS) {
            MBARRIER_WAIT_PARITY(sb + SMEM_EMPTY(ps), pph);
            MBARRIER_EXPECT_TX(sb + SMEM_FULL(ps), STAGE_BYTES);
            tma_load_2d(sb + SMEM_A(ps), &tmx, (kc + 2) * KC, m0, sb + SMEM_FULL(ps));
            tma_load_2d(sb + SMEM_B(ps), &tmw, (kc + 2) * KC, n0, sb + SMEM_FULL(ps));
            if (++ps == NSTAGES) { ps = 0; pph ^= 1; }
        }

        // rotated body: MMA current block, load next block behind it
        mma16(f0); load_frags(f1, sA, sB, 1);   // k8 = 0
        mma16(f1); load_frags(f0, sA, sB, 2);   // k8 = 1
        mma16(f0); load_frags(f1, sA, sB, 3);   // k8 = 2
        mma16(f1);                               // k8 = 3 (16 MMAs queued)

        // stage cs fully consumed (scoreboard drained by mma16 above)
        if (lid == 0) MBARRIER_ARRIVE(sb + SMEM_EMPTY(cs));
        if (++cs == NSTAGES) { cs = 0; cph ^= 1; }

        // cross-boundary prefetch hides wait+LDSM behind queued MMAs
        if (kc + 1 < KITERS) {
            MBARRIER_WAIT_PARITY(sb + SMEM_FULL(cs), cph);
            sA = sb + SMEM_A(cs);
            sB = sb + SMEM_B(cs);
            load_frags(f0, sA, sB, 0);
        }
    }

    // --- epilogue: acc + bias -> out ---
#pragma unroll
    for (int j = 0; j < 4; j++) {
        int col = n0 + wn0 + j * 8 + qid * 2;
        float2 bb = *(const float2*)(bias + col);
#pragma unroll
        for (int i = 0; i < 4; i++) {
            int row = m0 + wm0 + i * 16 + gid;
            float2 v0 = make_float2(acc[i][j][0] + bb.x, acc[i][j][1] + bb.y);
            float2 v1 = make_float2(acc[i][j][2] + bb.x, acc[i][j][3] + bb.y);
            *(float2*)(out + (size_t)row * MDIM + col) = v0;
            *(float2*)(out + (size_t)(row + 8) * MDIM + col) = v1;
        }
    }
}

// ============================================================================
// Host launch
// ============================================================================
typedef CUresult (*EncodeTiledFn)(
    CUtensorMap*, CUtensorMapDataType, cuuint32_t, void*,
    const cuuint64_t*, const cuuint64_t*, const cuuint32_t*, const cuuint32_t*,
    CUtensorMapInterleave, CUtensorMapSwizzle, CUtensorMapL2promotion,
    CUtensorMapFloatOOBfill);

static void make_map_2d(CUtensorMap* tm, const void* ptr,
                        unsigned long long d0, unsigned long long d1) {
    EncodeTiledFn fn = nullptr;
    cudaDriverEntryPointQueryResult qr;
    cudaGetDriverEntryPoint("cuTensorMapEncodeTiled", (void**)&fn,
                            cudaEnableDefault, &qr);
    cuuint64_t dims[2]    = {d0, d1};
    cuuint64_t strides[1] = {d0 * sizeof(float)};
    cuuint32_t box[2]     = {KC, TILE_M};
    cuuint32_t es[2]      = {1, 1};
    fn(tm, CU_TENSOR_MAP_DATA_TYPE_FLOAT32, 2, (void*)ptr, dims, strides, box, es,
       CU_TENSOR_MAP_INTERLEAVE_NONE, CU_TENSOR_MAP_SWIZZLE_128B,
       CU_TENSOR_MAP_L2_PROMOTION_L2_128B, CU_TENSOR_MAP_FLOAT_OOB_FILL_NONE);
}

extern "C" void kernel_launch(void* const* d_in, const int* in_sizes, int n_in,
                              void* d_out, int out_size) {
    const float* x = (const float*)d_in[0];
    const float* W = (const float*)d_in[1];
    const float* b = (const float*)d_in[2];
    const float* A = (const float*)d_in[3];
    const float* B = (const float*)d_in[4];
    float* out = (float*)d_out;
    int T = in_sizes[0] / KDIM;

    void* weff_ptr = nullptr;
    cudaGetSymbolAddress(&weff_ptr, g_Weff);

    int prep_blocks = (MDIM / PREP_MT) * (KDIM / PREP_KT);
    weff_prep_kernel<<<prep_blocks, 256>>>(W, A, B, (uint32_t*)weff_ptr);

    CUtensorMap tmx, tmw;
    make_map_2d(&tmx, x, KDIM, (unsigned long long)T);
    make_map_2d(&tmw, weff_ptr, KDIM, MDIM);

    cudaFuncSetAttribute(lora_gemm_kernel,
                         cudaFuncAttributeMaxDynamicSharedMemorySize, SMEM_BYTES);

    dim3 grid(MDIM / TILE_N, T / TILE_M);
    lora_gemm_kernel<<<grid, NTHREADS, SMEM_BYTES>>>(tmx, tmw, b, out);
}